// round 7
// baseline (speedup 1.0000x reference)
#include <cuda_runtime.h>
#include <cuda_bf16.h>
#include <float.h>

#define MAX_N 8192
#define N_CLASSES 1024
#define BLOCK 256
#define ROWS_PER_BLOCK 4                      // 8 warps, 2 per row
#define GRID (MAX_N / ROWS_PER_BLOCK)         // 2048

// Per-(class, half, lane) bitmask: bit (it*4+e) = targets[col]==class for
// col = half*4096 + it*128 + lane*4 + e.  1024*2*32 uint4 = 1 MB.
__device__ uint4        g_cmask[N_CLASSES * 64];
__device__ float        g_block_sum[GRID];
__device__ unsigned int g_done_count = 0;     // self-resets via atomicInc wrap

__global__ __launch_bounds__(256)
void build_masks_kernel(const int* __restrict__ targets, int n) {
    // One warp per (class, half): 2048 warps = 256 blocks x 8 warps.
    const int g    = blockIdx.x * 8 + (threadIdx.x >> 5);
    const int c    = g >> 1;
    const int half = g & 1;
    const int lid  = threadIdx.x & 31;
    const int jbeg = half * (MAX_N / 2);
    const int4* __restrict__ tp = reinterpret_cast<const int4*>(targets);

    unsigned int words[4];
    #pragma unroll
    for (int w = 0; w < 4; w++) {
        unsigned int acc = 0;
        #pragma unroll
        for (int s = 0; s < 8; s++) {
            const int j = jbeg + (w * 8 + s) * 128 + lid * 4;
            const int4 t = tp[j >> 2];
            unsigned int nib = (t.x == c) | ((t.y == c) << 1)
                             | ((t.z == c) << 2) | ((t.w == c) << 3);
            acc |= nib << (s * 4);
        }
        words[w] = acc;
    }
    g_cmask[c * 64 + half * 32 + lid] =
        make_uint4(words[0], words[1], words[2], words[3]);
}

__global__ __launch_bounds__(BLOCK, 7)
void triplet_fused_kernel(const float* __restrict__ sim,
                          const int* __restrict__ targets,
                          const int* __restrict__ idx,
                          float* __restrict__ out,
                          int n) {
    __shared__ float s_pos[BLOCK / 32];
    __shared__ float s_neg[BLOCK / 32];
    __shared__ float s_loss[ROWS_PER_BLOCK];
    __shared__ unsigned int s_is_last;

    const int tid  = threadIdx.x;
    const int wid  = tid >> 5;
    const int lid  = tid & 31;
    const int rloc = wid >> 1;
    const int half = wid & 1;

    const int row = blockIdx.x * ROWS_PER_BLOCK + rloc;
    const int my_t = targets[row];
    const int self_col = idx[row];
    const float* __restrict__ rp = sim + (size_t)self_col * (size_t)n;
    const int jbeg = half * (n >> 1);

    // Load this lane's 128-bit class mask (coalesced uint4).
    const uint4 m = g_cmask[my_t * 64 + half * 32 + lid];
    unsigned int wp[4] = {m.x, m.y, m.z, m.w};         // pos mask
    unsigned int wn[4] = {~m.x, ~m.y, ~m.z, ~m.w};     // neg mask (self already out)

    // Clear self bit from the pos mask (only the owning lane has it).
    {
        const int o = self_col - jbeg;
        if (o >= 0 && o < (n >> 1) && ((o >> 2) & 31) == lid) {
            const int b = ((o >> 7) << 2) | (o & 3);   // bit index 0..127
            const unsigned int bm = ~(1u << (b & 31));
            const int widx = b >> 5;
            if      (widx == 0) wp[0] &= bm;
            else if (widx == 1) wp[1] &= bm;
            else if (widx == 2) wp[2] &= bm;
            else                wp[3] &= bm;
        }
    }

    float pos =  FLT_MAX;
    float neg = -FLT_MAX;

    // Hot loop: ONE LDG.128 per iter; decisions come from registers.
    #pragma unroll
    for (int w = 0; w < 4; w++) {
        const unsigned int mp = wp[w];
        const unsigned int mn = wn[w];
        #pragma unroll 4
        for (int s = 0; s < 8; s++) {
            const int j = jbeg + (w * 8 + s) * 128 + lid * 4;
            const float4 v = __ldcs(reinterpret_cast<const float4*>(rp + j));
            const unsigned int np = mp >> (s * 4);
            const unsigned int nn = mn >> (s * 4);
            if (np & 1u) pos = fminf(pos, v.x);
            if (nn & 1u) neg = fmaxf(neg, v.x);
            if (np & 2u) pos = fminf(pos, v.y);
            if (nn & 2u) neg = fmaxf(neg, v.y);
            if (np & 4u) pos = fminf(pos, v.z);
            if (nn & 4u) neg = fmaxf(neg, v.z);
            if (np & 8u) pos = fminf(pos, v.w);
            if (nn & 8u) neg = fmaxf(neg, v.w);
        }
    }

    // Warp reduction.
    #pragma unroll
    for (int off = 16; off > 0; off >>= 1) {
        pos = fminf(pos, __shfl_xor_sync(0xFFFFFFFFu, pos, off));
        neg = fmaxf(neg, __shfl_xor_sync(0xFFFFFFFFu, neg, off));
    }
    if (lid == 0) { s_pos[wid] = pos; s_neg[wid] = neg; }
    __syncthreads();

    // Combine half-row partials; fixed order -> deterministic.
    if (tid < ROWS_PER_BLOCK) {
        const int w0 = tid * 2;
        const float p = fminf(s_pos[w0], s_pos[w0 + 1]);
        const float g = fmaxf(s_neg[w0], s_neg[w0 + 1]);
        s_loss[tid] = fmaxf(g - p + 0.1f, 0.0f);
    }
    __syncthreads();

    if (tid == 0) {
        float bs = 0.0f;
        #pragma unroll
        for (int r = 0; r < ROWS_PER_BLOCK; r++) bs += s_loss[r];
        g_block_sum[blockIdx.x] = bs;
        __threadfence();
        unsigned int prev = atomicInc(&g_done_count, GRID - 1);
        s_is_last = (prev == GRID - 1) ? 1u : 0u;
    }
    __syncthreads();

    // Last block: deterministic fixed-tree mean over 2048 partials.
    if (s_is_last) {
        __shared__ float s_sum[BLOCK / 32];
        const float4* bp = reinterpret_cast<const float4*>(g_block_sum);
        float4 a = __ldcg(bp + tid);
        float4 b = __ldcg(bp + tid + 256);
        float acc = ((a.x + a.y) + (a.z + a.w)) + ((b.x + b.y) + (b.z + b.w));
        #pragma unroll
        for (int off = 16; off > 0; off >>= 1)
            acc += __shfl_xor_sync(0xFFFFFFFFu, acc, off);
        if (lid == 0) s_sum[wid] = acc;
        __syncthreads();
        if (wid == 0) {
            acc = (lid < BLOCK / 32) ? s_sum[lid] : 0.0f;
            #pragma unroll
            for (int off = 4; off > 0; off >>= 1)
                acc += __shfl_xor_sync(0xFFFFFFFFu, acc, off);
            if (lid == 0) out[0] = acc / (float)n;
        }
    }
}

extern "C" void kernel_launch(void* const* d_in, const int* in_sizes, int n_in,
                              void* d_out, int out_size) {
    const float* sim     = (const float*)d_in[0];
    const int*   targets = (const int*)d_in[1];
    const int*   idx     = (const int*)d_in[2];
    float* out = (float*)d_out;

    const int n = in_sizes[1];   // 8192

    build_masks_kernel<<<N_CLASSES * 2 / 8, 256>>>(targets, n);
    triplet_fused_kernel<<<GRID, BLOCK>>>(sim, targets, idx, out, n);
}